// round 1
// baseline (speedup 1.0000x reference)
#include <cuda_runtime.h>
#include <math.h>

#define B_  4
#define T_  2048
#define D_  1024
#define H_  16
#define DH_ 64
#define M_  (B_ * T_)   // 8192

// Scratch (device globals; no allocation allowed)
__device__ float g_q[B_ * H_ * T_ * DH_];
__device__ float g_k[B_ * H_ * T_ * DH_];
__device__ float g_v[B_ * H_ * T_ * DH_];
__device__ float g_att[M_ * D_];

// ---------------------------------------------------------------------------
// GEMM: C = A(M x K) @ W^T, W stored (N x K) row-major. K = N = 1024, M = 8192.
// MODE 0: scatter into (B,H,T,Dh) layout (QKV projections)
// MODE 1: linear output + bias (final projection)
// ---------------------------------------------------------------------------
template <int MODE>
__global__ void __launch_bounds__(256) gemm_kernel(
    const float* __restrict__ A, const float* __restrict__ W,
    const float* __restrict__ bias, float* __restrict__ C)
{
    constexpr int K = 1024;
    __shared__ __align__(16) float As[16][68];
    __shared__ __align__(16) float Bs[16][68];

    const int tid = threadIdx.x;
    const int tx = tid & 15, ty = tid >> 4;
    const int m0 = blockIdx.y * 64, n0 = blockIdx.x * 64;

    const int lr = tid >> 2;          // 0..63 (row within tile)
    const int lc = (tid & 3) << 2;    // 0,4,8,12 (k offset)
    const float* Ap = A + (size_t)(m0 + lr) * K + lc;
    const float* Wp = W + (size_t)(n0 + lr) * K + lc;

    float acc[4][4] = {};

    for (int k0 = 0; k0 < K; k0 += 16) {
        float4 av = *(const float4*)(Ap + k0);
        float4 wv = *(const float4*)(Wp + k0);
        As[lc + 0][lr] = av.x; As[lc + 1][lr] = av.y;
        As[lc + 2][lr] = av.z; As[lc + 3][lr] = av.w;
        Bs[lc + 0][lr] = wv.x; Bs[lc + 1][lr] = wv.y;
        Bs[lc + 2][lr] = wv.z; Bs[lc + 3][lr] = wv.w;
        __syncthreads();

        #pragma unroll
        for (int kk = 0; kk < 16; kk++) {
            float4 a = *(const float4*)&As[kk][ty << 2];
            float4 b = *(const float4*)&Bs[kk][tx << 2];
            float aa[4] = {a.x, a.y, a.z, a.w};
            float bb[4] = {b.x, b.y, b.z, b.w};
            #pragma unroll
            for (int i = 0; i < 4; i++) {
                #pragma unroll
                for (int j = 0; j < 4; j++) acc[i][j] += aa[i] * bb[j];
            }
        }
        __syncthreads();
    }

    if (MODE == 0) {
        // scatter: m = b*T + t ; n = h*Dh + d -> out[((b*H+h)*T + t)*Dh + d]
        const int n = n0 + (tx << 2);
        const int h = n >> 6, d = n & 63;
        #pragma unroll
        for (int i = 0; i < 4; i++) {
            int m = m0 + (ty << 2) + i;
            int bb_ = m >> 11, t = m & 2047;
            float4 vo = make_float4(acc[i][0], acc[i][1], acc[i][2], acc[i][3]);
            *(float4*)(C + ((size_t)((bb_ << 4) + h) * T_ + t) * DH_ + d) = vo;
        }
    } else {
        const int n = n0 + (tx << 2);
        float4 b4 = *(const float4*)(bias + n);
        #pragma unroll
        for (int i = 0; i < 4; i++) {
            int m = m0 + (ty << 2) + i;
            float4 vo = make_float4(acc[i][0] + b4.x, acc[i][1] + b4.y,
                                    acc[i][2] + b4.z, acc[i][3] + b4.w);
            *(float4*)(C + (size_t)m * D_ + n) = vo;
        }
    }
}

// ---------------------------------------------------------------------------
// Flash-style ALiBi attention.
// grid = (T/64, B*H), block = 256 threads (16x16), 4x4 micro-tiles.
// Online softmax: each row owned by a fixed 16-lane half-warp; m/l replicated
// in registers via shfl reductions.
// ---------------------------------------------------------------------------
#define SMEM_ATTN (4 * 64 * 68 * 4)

__global__ void __launch_bounds__(256) attn_kernel(
    const float* __restrict__ q, const float* __restrict__ k,
    const float* __restrict__ v, float* __restrict__ out)
{
    extern __shared__ float sm[];
    float* Qs = sm;               // [64][68]  Qs[d][qrow]   (d-major)
    float* Ks = sm + 64 * 68;     // [64][68]  Ks[d][krow]   (d-major)
    float* Vs = sm + 2 * 64 * 68; // [64][68]  Vs[krow][d]   (natural)
    float* Ps = sm + 3 * 64 * 68; // [64][68]  Ps[qrow][krow]

    const int tid = threadIdx.x;
    const int tx = tid & 15, ty = tid >> 4;
    const int q0 = blockIdx.x * 64;
    const int bh = blockIdx.y;
    const int h = bh & (H_ - 1);
    const float slope = exp2f(-0.5f * (float)(h + 1));

    const float* qb = q + (size_t)bh * T_ * DH_;
    const float* kb = k + (size_t)bh * T_ * DH_;
    const float* vb = v + (size_t)bh * T_ * DH_;

    const int lr = tid >> 4;          // 0..15
    const int lc = (tid & 15) << 2;   // 0..60

    // load Q tile transposed: Qs[d][qrow]
    #pragma unroll
    for (int rep = 0; rep < 4; rep++) {
        int row = lr + (rep << 4);
        float4 qv = *(const float4*)(qb + (size_t)(q0 + row) * DH_ + lc);
        Qs[(lc + 0) * 68 + row] = qv.x;
        Qs[(lc + 1) * 68 + row] = qv.y;
        Qs[(lc + 2) * 68 + row] = qv.z;
        Qs[(lc + 3) * 68 + row] = qv.w;
    }

    float o[4][4] = {};
    float mi[4], li[4];
    #pragma unroll
    for (int i = 0; i < 4; i++) { mi[i] = -1e30f; li[i] = 0.f; }

    for (int kt0 = 0; kt0 < T_; kt0 += 64) {
        // load K (transposed) and V (natural)
        #pragma unroll
        for (int rep = 0; rep < 4; rep++) {
            int row = lr + (rep << 4);
            float4 kv = *(const float4*)(kb + (size_t)(kt0 + row) * DH_ + lc);
            Ks[(lc + 0) * 68 + row] = kv.x;
            Ks[(lc + 1) * 68 + row] = kv.y;
            Ks[(lc + 2) * 68 + row] = kv.z;
            Ks[(lc + 3) * 68 + row] = kv.w;
            float4 vv = *(const float4*)(vb + (size_t)(kt0 + row) * DH_ + lc);
            *(float4*)&Vs[row * 68 + lc] = vv;
        }
        __syncthreads();

        // S = Q @ K^T  (d-major inner loop)
        float s[4][4] = {};
        #pragma unroll 16
        for (int d = 0; d < 64; d++) {
            float4 a = *(const float4*)&Qs[d * 68 + (ty << 2)];
            float4 b = *(const float4*)&Ks[d * 68 + (tx << 2)];
            float aa[4] = {a.x, a.y, a.z, a.w};
            float bb[4] = {b.x, b.y, b.z, b.w};
            #pragma unroll
            for (int i = 0; i < 4; i++) {
                #pragma unroll
                for (int j = 0; j < 4; j++) s[i][j] += aa[i] * bb[j];
            }
        }

        // scale + ALiBi + online softmax (half-warp per row group)
        #pragma unroll
        for (int i = 0; i < 4; i++) {
            int qg = q0 + (ty << 2) + i;
            #pragma unroll
            for (int j = 0; j < 4; j++) {
                int kg = kt0 + (tx << 2) + j;
                s[i][j] = s[i][j] * 0.125f - slope * fabsf((float)(qg - kg));
            }
            float mx = fmaxf(fmaxf(s[i][0], s[i][1]), fmaxf(s[i][2], s[i][3]));
            mx = fmaxf(mx, __shfl_xor_sync(0xffffffffu, mx, 1));
            mx = fmaxf(mx, __shfl_xor_sync(0xffffffffu, mx, 2));
            mx = fmaxf(mx, __shfl_xor_sync(0xffffffffu, mx, 4));
            mx = fmaxf(mx, __shfl_xor_sync(0xffffffffu, mx, 8));
            float mnew  = fmaxf(mi[i], mx);
            float alpha = __expf(mi[i] - mnew);
            float rs = 0.f;
            #pragma unroll
            for (int j = 0; j < 4; j++) {
                float p = __expf(s[i][j] - mnew);
                s[i][j] = p; rs += p;
            }
            rs += __shfl_xor_sync(0xffffffffu, rs, 1);
            rs += __shfl_xor_sync(0xffffffffu, rs, 2);
            rs += __shfl_xor_sync(0xffffffffu, rs, 4);
            rs += __shfl_xor_sync(0xffffffffu, rs, 8);
            li[i] = li[i] * alpha + rs;
            mi[i] = mnew;
            #pragma unroll
            for (int j = 0; j < 4; j++) o[i][j] *= alpha;
            *(float4*)&Ps[(size_t)((ty << 2) + i) * 68 + (tx << 2)] =
                make_float4(s[i][0], s[i][1], s[i][2], s[i][3]);
        }
        __syncthreads();

        // O += P @ V
        #pragma unroll 16
        for (int kk = 0; kk < 64; kk++) {
            float4 bv = *(const float4*)&Vs[kk * 68 + (tx << 2)];
            float bb[4] = {bv.x, bv.y, bv.z, bv.w};
            #pragma unroll
            for (int i = 0; i < 4; i++) {
                float a = Ps[((ty << 2) + i) * 68 + kk];
                #pragma unroll
                for (int j = 0; j < 4; j++) o[i][j] += a * bb[j];
            }
        }
        __syncthreads();
    }

    // epilogue: normalize and write to (B, T, H*Dh)
    const int bb_ = bh >> 4;
    #pragma unroll
    for (int i = 0; i < 4; i++) {
        float invl = 1.f / li[i];
        int t = q0 + (ty << 2) + i;
        float4 vo = make_float4(o[i][0] * invl, o[i][1] * invl,
                                o[i][2] * invl, o[i][3] * invl);
        *(float4*)(out + ((size_t)(bb_ * T_ + t)) * D_ + h * DH_ + (tx << 2)) = vo;
    }
}

// ---------------------------------------------------------------------------
extern "C" void kernel_launch(void* const* d_in, const int* in_sizes, int n_in,
                              void* d_out, int out_size)
{
    const float* x  = (const float*)d_in[0];
    const float* wq = (const float*)d_in[1];
    const float* wk = (const float*)d_in[2];
    const float* wv = (const float*)d_in[3];
    const float* wo = (const float*)d_in[4];
    const float* bo = (const float*)d_in[5];

    float *qp, *kp, *vp, *ap;
    cudaGetSymbolAddress((void**)&qp, g_q);
    cudaGetSymbolAddress((void**)&kp, g_k);
    cudaGetSymbolAddress((void**)&vp, g_v);
    cudaGetSymbolAddress((void**)&ap, g_att);

    dim3 gg(D_ / 64, M_ / 64);   // (16, 128)
    gemm_kernel<0><<<gg, 256>>>(x, wq, nullptr, qp);
    gemm_kernel<0><<<gg, 256>>>(x, wk, nullptr, kp);
    gemm_kernel<0><<<gg, 256>>>(x, wv, nullptr, vp);

    cudaFuncSetAttribute(attn_kernel,
                         cudaFuncAttributeMaxDynamicSharedMemorySize, SMEM_ATTN);
    attn_kernel<<<dim3(T_ / 64, B_ * H_), 256, SMEM_ATTN>>>(qp, kp, vp, ap);

    gemm_kernel<1><<<gg, 256>>>(ap, wo, bo, (float*)d_out);
}

// round 2
// speedup vs baseline: 1.5712x; 1.5712x over previous
#include <cuda_runtime.h>
#include <math.h>
#include <stdint.h>

#define B_  4
#define T_  2048
#define D_  1024
#define H_  16
#define DH_ 64
#define M_  (B_ * T_)   // 8192

// Scratch (device globals; no allocation allowed)
__device__ float g_q[B_ * H_ * T_ * DH_];
__device__ float g_k[B_ * H_ * T_ * DH_];
__device__ float g_v[B_ * H_ * T_ * DH_];
__device__ float g_att[M_ * D_];
__device__ float g_x[M_ * D_];          // tf32-rounded x
__device__ float g_wq[D_ * D_];
__device__ float g_wk[D_ * D_];
__device__ float g_wv[D_ * D_];
__device__ float g_wo[D_ * D_];

__device__ __forceinline__ uint32_t f2tf(float f) {
    uint32_t u;
    asm("cvt.rna.tf32.f32 %0, %1;" : "=r"(u) : "f"(f));
    return u;
}

// ---------------------------------------------------------------------------
// Elementwise tf32 rounding (RNA) pass: removes truncation bias so the HMMA
// can consume raw bits.
// ---------------------------------------------------------------------------
__global__ void round_tf32_kernel(const float* __restrict__ in,
                                  float* __restrict__ out, int n4)
{
    int i = blockIdx.x * blockDim.x + threadIdx.x;
    if (i < n4) {
        float4 v = ((const float4*)in)[i];
        v.x = __uint_as_float(f2tf(v.x));
        v.y = __uint_as_float(f2tf(v.y));
        v.z = __uint_as_float(f2tf(v.z));
        v.w = __uint_as_float(f2tf(v.w));
        ((float4*)out)[i] = v;
    }
}

// ---------------------------------------------------------------------------
// Tensor-core tf32 GEMM: C = A(MxK) @ W^T, W stored (N x K) row-major.
// BM=BN=128, BK=32. 256 threads = 8 warps (4x2), warp tile 32x64.
// Inputs must be pre-rounded to tf32 grid.
// MODE 0: scatter into (B,H,T,Dh); MODE 1: linear + bias.
// ---------------------------------------------------------------------------
#define SA 36                     // smem row stride (floats), conflict-free
#define TILE_U32 (128 * SA)       // 4608 per matrix
#define GEMM_SMEM (2 * 2 * TILE_U32 * 4)  // 73728 bytes

template <int MODE>
__global__ void __launch_bounds__(256, 2) gemm_tc(
    const float* __restrict__ A, const float* __restrict__ W,
    const float* __restrict__ bias, float* __restrict__ C)
{
    constexpr int K = 1024;
    extern __shared__ uint32_t sm[];

    const int tid  = threadIdx.x;
    const int lane = tid & 31;
    const int warp = tid >> 5;
    const int wm   = warp & 3;        // 0..3
    const int wn   = warp >> 2;       // 0..1
    const int m0   = blockIdx.y * 128;
    const int n0   = blockIdx.x * 128;

    const int k4   = (tid & 7) * 4;   // k offset of 16B chunk
    const int mrow = tid >> 3;        // 0..31

    auto load_tile = [&](int k0, int s) {
        uint32_t* As = sm + s * 2 * TILE_U32;
        uint32_t* Bs = As + TILE_U32;
        #pragma unroll
        for (int t = 0; t < 4; t++) {
            int m = mrow + t * 32;
            const float* ga = A + (size_t)(m0 + m) * K + k0 + k4;
            unsigned sa = (unsigned)__cvta_generic_to_shared(&As[m * SA + k4]);
            asm volatile("cp.async.cg.shared.global [%0], [%1], 16;" :: "r"(sa), "l"(ga));
            const float* gb = W + (size_t)(n0 + m) * K + k0 + k4;
            unsigned sb = (unsigned)__cvta_generic_to_shared(&Bs[m * SA + k4]);
            asm volatile("cp.async.cg.shared.global [%0], [%1], 16;" :: "r"(sb), "l"(gb));
        }
        asm volatile("cp.async.commit_group;");
    };

    float c[2][8][4] = {};

    load_tile(0, 0);

    const int r    = lane >> 2;   // 0..7
    const int csel = lane & 3;    // 0..3

    for (int it = 0; it < K / 32; ++it) {
        if (it + 1 < K / 32) {
            load_tile((it + 1) * 32, (it + 1) & 1);
            asm volatile("cp.async.wait_group 1;");
        } else {
            asm volatile("cp.async.wait_group 0;");
        }
        __syncthreads();

        const uint32_t* As = sm + (it & 1) * 2 * TILE_U32;
        const uint32_t* Bs = As + TILE_U32;

        #pragma unroll
        for (int kk = 0; kk < 32; kk += 8) {
            uint32_t a[2][4], b[8][2];
            #pragma unroll
            for (int mi = 0; mi < 2; mi++) {
                const uint32_t* p = As + (wm * 32 + mi * 16 + r) * SA + kk + csel;
                a[mi][0] = p[0];
                a[mi][2] = p[4];
                a[mi][1] = p[8 * SA];
                a[mi][3] = p[8 * SA + 4];
            }
            #pragma unroll
            for (int ni = 0; ni < 8; ni++) {
                const uint32_t* p = Bs + (wn * 64 + ni * 8 + r) * SA + kk + csel;
                b[ni][0] = p[0];
                b[ni][1] = p[4];
            }
            #pragma unroll
            for (int mi = 0; mi < 2; mi++)
                #pragma unroll
                for (int ni = 0; ni < 8; ni++)
                    asm volatile(
                        "mma.sync.aligned.m16n8k8.row.col.f32.tf32.tf32.f32 "
                        "{%0,%1,%2,%3}, {%4,%5,%6,%7}, {%8,%9}, {%0,%1,%2,%3};"
                        : "+f"(c[mi][ni][0]), "+f"(c[mi][ni][1]),
                          "+f"(c[mi][ni][2]), "+f"(c[mi][ni][3])
                        : "r"(a[mi][0]), "r"(a[mi][1]), "r"(a[mi][2]), "r"(a[mi][3]),
                          "r"(b[ni][0]), "r"(b[ni][1]));
        }
        __syncthreads();
    }

    // epilogue
    const int cq = (lane & 3) * 2;
    #pragma unroll
    for (int mi = 0; mi < 2; mi++) {
        #pragma unroll
        for (int ni = 0; ni < 8; ni++) {
            int n = n0 + wn * 64 + ni * 8 + cq;
            #pragma unroll
            for (int half = 0; half < 2; half++) {
                int m = m0 + wm * 32 + mi * 16 + r + half * 8;
                float2 vo = make_float2(c[mi][ni][half * 2],
                                        c[mi][ni][half * 2 + 1]);
                if (MODE == 0) {
                    int h = n >> 6, d = n & 63;
                    int bb = m >> 11, t = m & 2047;
                    *(float2*)(C + ((size_t)((bb << 4) + h) * T_ + t) * DH_ + d) = vo;
                } else {
                    float2 b2 = *(const float2*)(bias + n);
                    vo.x += b2.x; vo.y += b2.y;
                    *(float2*)(C + (size_t)m * D_ + n) = vo;
                }
            }
        }
    }
}

// ---------------------------------------------------------------------------
// Flash-style ALiBi attention (unchanged except tf32 rounding in epilogue).
// grid = (T/64, B*H), block = 256 threads (16x16), 4x4 micro-tiles.
// ---------------------------------------------------------------------------
#define SMEM_ATTN (4 * 64 * 68 * 4)

__global__ void __launch_bounds__(256) attn_kernel(
    const float* __restrict__ q, const float* __restrict__ k,
    const float* __restrict__ v, float* __restrict__ out)
{
    extern __shared__ float smf[];
    float* Qs = smf;               // [64][68]  Qs[d][qrow]
    float* Ks = smf + 64 * 68;     // [64][68]  Ks[d][krow]
    float* Vs = smf + 2 * 64 * 68; // [64][68]  Vs[krow][d]
    float* Ps = smf + 3 * 64 * 68; // [64][68]  Ps[qrow][krow]

    const int tid = threadIdx.x;
    const int tx = tid & 15, ty = tid >> 4;
    const int q0 = blockIdx.x * 64;
    const int bh = blockIdx.y;
    const int h = bh & (H_ - 1);
    const float slope = exp2f(-0.5f * (float)(h + 1));

    const float* qb = q + (size_t)bh * T_ * DH_;
    const float* kb = k + (size_t)bh * T_ * DH_;
    const float* vb = v + (size_t)bh * T_ * DH_;

    const int lr = tid >> 4;
    const int lc = (tid & 15) << 2;

    #pragma unroll
    for (int rep = 0; rep < 4; rep++) {
        int row = lr + (rep << 4);
        float4 qv = *(const float4*)(qb + (size_t)(q0 + row) * DH_ + lc);
        Qs[(lc + 0) * 68 + row] = qv.x;
        Qs[(lc + 1) * 68 + row] = qv.y;
        Qs[(lc + 2) * 68 + row] = qv.z;
        Qs[(lc + 3) * 68 + row] = qv.w;
    }

    float o[4][4] = {};
    float mi[4], li[4];
    #pragma unroll
    for (int i = 0; i < 4; i++) { mi[i] = -1e30f; li[i] = 0.f; }

    for (int kt0 = 0; kt0 < T_; kt0 += 64) {
        #pragma unroll
        for (int rep = 0; rep < 4; rep++) {
            int row = lr + (rep << 4);
            float4 kv = *(const float4*)(kb + (size_t)(kt0 + row) * DH_ + lc);
            Ks[(lc + 0) * 68 + row] = kv.x;
            Ks[(lc + 1) * 68 + row] = kv.y;
            Ks[(lc + 2) * 68 + row] = kv.z;
            Ks[(lc + 3) * 68 + row] = kv.w;
            float4 vv = *(const float4*)(vb + (size_t)(kt0 + row) * DH_ + lc);
            *(float4*)&Vs[row * 68 + lc] = vv;
        }
        __syncthreads();

        float s[4][4] = {};
        #pragma unroll 16
        for (int d = 0; d < 64; d++) {
            float4 a = *(const float4*)&Qs[d * 68 + (ty << 2)];
            float4 b = *(const float4*)&Ks[d * 68 + (tx << 2)];
            float aa[4] = {a.x, a.y, a.z, a.w};
            float bb[4] = {b.x, b.y, b.z, b.w};
            #pragma unroll
            for (int i = 0; i < 4; i++) {
                #pragma unroll
                for (int j = 0; j < 4; j++) s[i][j] += aa[i] * bb[j];
            }
        }

        #pragma unroll
        for (int i = 0; i < 4; i++) {
            int qg = q0 + (ty << 2) + i;
            #pragma unroll
            for (int j = 0; j < 4; j++) {
                int kg = kt0 + (tx << 2) + j;
                s[i][j] = s[i][j] * 0.125f - slope * fabsf((float)(qg - kg));
            }
            float mx = fmaxf(fmaxf(s[i][0], s[i][1]), fmaxf(s[i][2], s[i][3]));
            mx = fmaxf(mx, __shfl_xor_sync(0xffffffffu, mx, 1));
            mx = fmaxf(mx, __shfl_xor_sync(0xffffffffu, mx, 2));
            mx = fmaxf(mx, __shfl_xor_sync(0xffffffffu, mx, 4));
            mx = fmaxf(mx, __shfl_xor_sync(0xffffffffu, mx, 8));
            float mnew  = fmaxf(mi[i], mx);
            float alpha = __expf(mi[i] - mnew);
            float rs = 0.f;
            #pragma unroll
            for (int j = 0; j < 4; j++) {
                float p = __expf(s[i][j] - mnew);
                s[i][j] = p; rs += p;
            }
            rs += __shfl_xor_sync(0xffffffffu, rs, 1);
            rs += __shfl_xor_sync(0xffffffffu, rs, 2);
            rs += __shfl_xor_sync(0xffffffffu, rs, 4);
            rs += __shfl_xor_sync(0xffffffffu, rs, 8);
            li[i] = li[i] * alpha + rs;
            mi[i] = mnew;
            #pragma unroll
            for (int j = 0; j < 4; j++) o[i][j] *= alpha;
            *(float4*)&Ps[(size_t)((ty << 2) + i) * 68 + (tx << 2)] =
                make_float4(s[i][0], s[i][1], s[i][2], s[i][3]);
        }
        __syncthreads();

        #pragma unroll 16
        for (int kk = 0; kk < 64; kk++) {
            float4 bv = *(const float4*)&Vs[kk * 68 + (tx << 2)];
            float bb[4] = {bv.x, bv.y, bv.z, bv.w};
            #pragma unroll
            for (int i = 0; i < 4; i++) {
                float a = Ps[((ty << 2) + i) * 68 + kk];
                #pragma unroll
                for (int j = 0; j < 4; j++) o[i][j] += a * bb[j];
            }
        }
        __syncthreads();
    }

    // epilogue: normalize, round to tf32 grid (feeds tf32 output GEMM)
    const int bb_ = bh >> 4;
    #pragma unroll
    for (int i = 0; i < 4; i++) {
        float invl = 1.f / li[i];
        int t = q0 + (ty << 2) + i;
        float4 vo;
        vo.x = __uint_as_float(f2tf(o[i][0] * invl));
        vo.y = __uint_as_float(f2tf(o[i][1] * invl));
        vo.z = __uint_as_float(f2tf(o[i][2] * invl));
        vo.w = __uint_as_float(f2tf(o[i][3] * invl));
        *(float4*)(out + ((size_t)(bb_ * T_ + t)) * D_ + h * DH_ + (tx << 2)) = vo;
    }
}

// ---------------------------------------------------------------------------
extern "C" void kernel_launch(void* const* d_in, const int* in_sizes, int n_in,
                              void* d_out, int out_size)
{
    const float* x  = (const float*)d_in[0];
    const float* wq = (const float*)d_in[1];
    const float* wk = (const float*)d_in[2];
    const float* wv = (const float*)d_in[3];
    const float* wo = (const float*)d_in[4];
    const float* bo = (const float*)d_in[5];

    float *qp, *kp, *vp, *ap, *xp, *wqp, *wkp, *wvp, *wop;
    cudaGetSymbolAddress((void**)&qp,  g_q);
    cudaGetSymbolAddress((void**)&kp,  g_k);
    cudaGetSymbolAddress((void**)&vp,  g_v);
    cudaGetSymbolAddress((void**)&ap,  g_att);
    cudaGetSymbolAddress((void**)&xp,  g_x);
    cudaGetSymbolAddress((void**)&wqp, g_wq);
    cudaGetSymbolAddress((void**)&wkp, g_wk);
    cudaGetSymbolAddress((void**)&wvp, g_wv);
    cudaGetSymbolAddress((void**)&wop, g_wo);

    // tf32-round inputs (removes HMMA truncation bias)
    const int nx4 = M_ * D_ / 4, nw4 = D_ * D_ / 4;
    round_tf32_kernel<<<(nx4 + 255) / 256, 256>>>(x,  xp,  nx4);
    round_tf32_kernel<<<(nw4 + 255) / 256, 256>>>(wq, wqp, nw4);
    round_tf32_kernel<<<(nw4 + 255) / 256, 256>>>(wk, wkp, nw4);
    round_tf32_kernel<<<(nw4 + 255) / 256, 256>>>(wv, wvp, nw4);
    round_tf32_kernel<<<(nw4 + 255) / 256, 256>>>(wo, wop, nw4);

    cudaFuncSetAttribute(gemm_tc<0>,
                         cudaFuncAttributeMaxDynamicSharedMemorySize, GEMM_SMEM);
    cudaFuncSetAttribute(gemm_tc<1>,
                         cudaFuncAttributeMaxDynamicSharedMemorySize, GEMM_SMEM);

    dim3 gg(D_ / 128, M_ / 128);   // (8, 64)
    gemm_tc<0><<<gg, 256, GEMM_SMEM>>>(xp, wqp, nullptr, qp);
    gemm_tc<0><<<gg, 256, GEMM_SMEM>>>(xp, wkp, nullptr, kp);
    gemm_tc<0><<<gg, 256, GEMM_SMEM>>>(xp, wvp, nullptr, vp);

    cudaFuncSetAttribute(attn_kernel,
                         cudaFuncAttributeMaxDynamicSharedMemorySize, SMEM_ATTN);
    attn_kernel<<<dim3(T_ / 64, B_ * H_), 256, SMEM_ATTN>>>(qp, kp, vp, ap);

    gemm_tc<1><<<gg, 256, GEMM_SMEM>>>(ap, wop, bo, (float*)d_out);
}

// round 3
// speedup vs baseline: 2.8445x; 1.8103x over previous
#include <cuda_runtime.h>
#include <math.h>
#include <stdint.h>

#define B_  4
#define T_  2048
#define D_  1024
#define H_  16
#define DH_ 64
#define M_  (B_ * T_)   // 8192

// Scratch (device globals; no allocation allowed)
__device__ float g_q[B_ * H_ * T_ * DH_];
__device__ float g_k[B_ * H_ * T_ * DH_];
__device__ float g_v[B_ * H_ * T_ * DH_];
__device__ float g_att[M_ * D_];
__device__ float g_x[M_ * D_];
__device__ float g_wq[D_ * D_];
__device__ float g_wk[D_ * D_];
__device__ float g_wv[D_ * D_];
__device__ float g_wo[D_ * D_];

__device__ __forceinline__ uint32_t f2tf(float f) {
    uint32_t u;
    asm("cvt.rna.tf32.f32 %0, %1;" : "=r"(u) : "f"(f));
    return u;
}

// fast 2^t on the FMA pipe (no MUFU). |err| ~2e-6 rel. t <= 0 expected.
__device__ __forceinline__ float fexp2(float t) {
    t = fmaxf(t, -126.0f);
    float nf = t + 12582912.0f;              // round-to-nearest-int magic
    float f  = t - (nf - 12582912.0f);       // f in [-0.5, 0.5]
    float p  = 0.0013333558f;
    p = fmaf(p, f, 0.0096181291f);
    p = fmaf(p, f, 0.0555041087f);
    p = fmaf(p, f, 0.2402265070f);
    p = fmaf(p, f, 0.6931471806f);
    p = fmaf(p, f, 1.0f);
    return __int_as_float(__float_as_int(p) + (__float_as_int(nf) << 23));
}

// ---------------------------------------------------------------------------
__global__ void round_tf32_kernel(const float* __restrict__ in,
                                  float* __restrict__ out, int n4)
{
    int i = blockIdx.x * blockDim.x + threadIdx.x;
    if (i < n4) {
        float4 v = ((const float4*)in)[i];
        v.x = __uint_as_float(f2tf(v.x));
        v.y = __uint_as_float(f2tf(v.y));
        v.z = __uint_as_float(f2tf(v.z));
        v.w = __uint_as_float(f2tf(v.w));
        ((float4*)out)[i] = v;
    }
}

// ---------------------------------------------------------------------------
// Tensor-core tf32 GEMM: C = A(MxK) @ W^T  (unchanged from round 2)
// ---------------------------------------------------------------------------
#define SA 36
#define TILE_U32 (128 * SA)
#define GEMM_SMEM (2 * 2 * TILE_U32 * 4)

template <int MODE>
__global__ void __launch_bounds__(256, 2) gemm_tc(
    const float* __restrict__ A, const float* __restrict__ W,
    const float* __restrict__ bias, float* __restrict__ C)
{
    constexpr int K = 1024;
    extern __shared__ uint32_t sm[];

    const int tid  = threadIdx.x;
    const int lane = tid & 31;
    const int warp = tid >> 5;
    const int wm   = warp & 3;
    const int wn   = warp >> 2;
    const int m0   = blockIdx.y * 128;
    const int n0   = blockIdx.x * 128;

    const int k4   = (tid & 7) * 4;
    const int mrow = tid >> 3;

    auto load_tile = [&](int k0, int s) {
        uint32_t* As = sm + s * 2 * TILE_U32;
        uint32_t* Bs = As + TILE_U32;
        #pragma unroll
        for (int t = 0; t < 4; t++) {
            int m = mrow + t * 32;
            const float* ga = A + (size_t)(m0 + m) * K + k0 + k4;
            unsigned sa = (unsigned)__cvta_generic_to_shared(&As[m * SA + k4]);
            asm volatile("cp.async.cg.shared.global [%0], [%1], 16;" :: "r"(sa), "l"(ga));
            const float* gb = W + (size_t)(n0 + m) * K + k0 + k4;
            unsigned sb = (unsigned)__cvta_generic_to_shared(&Bs[m * SA + k4]);
            asm volatile("cp.async.cg.shared.global [%0], [%1], 16;" :: "r"(sb), "l"(gb));
        }
        asm volatile("cp.async.commit_group;");
    };

    float c[2][8][4] = {};
    load_tile(0, 0);

    const int r    = lane >> 2;
    const int csel = lane & 3;

    for (int it = 0; it < K / 32; ++it) {
        if (it + 1 < K / 32) {
            load_tile((it + 1) * 32, (it + 1) & 1);
            asm volatile("cp.async.wait_group 1;");
        } else {
            asm volatile("cp.async.wait_group 0;");
        }
        __syncthreads();

        const uint32_t* As = sm + (it & 1) * 2 * TILE_U32;
        const uint32_t* Bs = As + TILE_U32;

        #pragma unroll
        for (int kk = 0; kk < 32; kk += 8) {
            uint32_t a[2][4], b[8][2];
            #pragma unroll
            for (int mi = 0; mi < 2; mi++) {
                const uint32_t* p = As + (wm * 32 + mi * 16 + r) * SA + kk + csel;
                a[mi][0] = p[0];
                a[mi][2] = p[4];
                a[mi][1] = p[8 * SA];
                a[mi][3] = p[8 * SA + 4];
            }
            #pragma unroll
            for (int ni = 0; ni < 8; ni++) {
                const uint32_t* p = Bs + (wn * 64 + ni * 8 + r) * SA + kk + csel;
                b[ni][0] = p[0];
                b[ni][1] = p[4];
            }
            #pragma unroll
            for (int mi = 0; mi < 2; mi++)
                #pragma unroll
                for (int ni = 0; ni < 8; ni++)
                    asm volatile(
                        "mma.sync.aligned.m16n8k8.row.col.f32.tf32.tf32.f32 "
                        "{%0,%1,%2,%3}, {%4,%5,%6,%7}, {%8,%9}, {%0,%1,%2,%3};"
                        : "+f"(c[mi][ni][0]), "+f"(c[mi][ni][1]),
                          "+f"(c[mi][ni][2]), "+f"(c[mi][ni][3])
                        : "r"(a[mi][0]), "r"(a[mi][1]), "r"(a[mi][2]), "r"(a[mi][3]),
                          "r"(b[ni][0]), "r"(b[ni][1]));
        }
        __syncthreads();
    }

    const int cq = (lane & 3) * 2;
    #pragma unroll
    for (int mi = 0; mi < 2; mi++) {
        #pragma unroll
        for (int ni = 0; ni < 8; ni++) {
            int n = n0 + wn * 64 + ni * 8 + cq;
            #pragma unroll
            for (int half = 0; half < 2; half++) {
                int m = m0 + wm * 32 + mi * 16 + r + half * 8;
                float2 vo = make_float2(c[mi][ni][half * 2],
                                        c[mi][ni][half * 2 + 1]);
                if (MODE == 0) {
                    int h = n >> 6, d = n & 63;
                    int bb = m >> 11, t = m & 2047;
                    *(float2*)(C + ((size_t)((bb << 4) + h) * T_ + t) * DH_ + d) = vo;
                } else {
                    float2 b2 = *(const float2*)(bias + n);
                    vo.x += b2.x; vo.y += b2.y;
                    *(float2*)(C + (size_t)m * D_ + n) = vo;
                }
            }
        }
    }
}

// ---------------------------------------------------------------------------
// Tensor-core flash attention with ALiBi, log2-domain softmax, poly exp2.
// grid (T/128, B*H), 256 threads = 8 warps; warp w owns q-rows [w*16, w*16+16).
// KV processed in chunks of 64 tokens; K smem stride 68, V stride 72
// (both conflict-free for the B-fragment access patterns).
// ---------------------------------------------------------------------------
#define QSC 0.1803368801111154f   /* 0.125 * log2(e) */

__global__ void __launch_bounds__(256) attn_tc(
    const float* __restrict__ q, const float* __restrict__ k,
    const float* __restrict__ v, float* __restrict__ out)
{
    __shared__ float Ks[64][68];
    __shared__ float Vs[64][72];

    const int tid  = threadIdx.x;
    const int lane = tid & 31;
    const int warp = tid >> 5;
    const int q0   = blockIdx.x * 128;
    const int bh   = blockIdx.y;
    const int h    = bh & (H_ - 1);
    const float slope2 = exp2f(-0.5f * (float)(h + 1)) * 1.4426950408889634f;

    const float* qb = q + (size_t)bh * T_ * DH_;
    const float* kb = k + (size_t)bh * T_ * DH_;
    const float* vb = v + (size_t)bh * T_ * DH_;

    const int r   = lane >> 2;       // 0..7
    const int ql  = lane & 3;        // 0..3
    const int wrow = q0 + warp * 16; // warp's first q row

    // ---- Q fragments (A operand), scale*log2e folded, tf32-rounded --------
    uint32_t qa[8][4];
    #pragma unroll
    for (int kt = 0; kt < 8; kt++) {
        const float* p0 = qb + (size_t)(wrow + r) * DH_ + kt * 8 + ql;
        qa[kt][0] = f2tf(p0[0] * QSC);
        qa[kt][2] = f2tf(p0[4] * QSC);
        qa[kt][1] = f2tf(p0[8 * DH_] * QSC);
        qa[kt][3] = f2tf(p0[8 * DH_ + 4] * QSC);
    }

    // ---- K/V chunk loader (register prefetch pipeline) --------------------
    const int ldrow = tid >> 2;          // 0..63
    const int ldc   = (tid & 3) * 16;    // 0,16,32,48
    float4 kr[4], vr[4];

    #pragma unroll
    for (int j = 0; j < 4; j++) {
        kr[j] = *(const float4*)(kb + (size_t)ldrow * DH_ + ldc + 4 * j);
        vr[j] = *(const float4*)(vb + (size_t)ldrow * DH_ + ldc + 4 * j);
    }

    float o[8][4] = {};
    float m0 = -1e30f, m1 = -1e30f, l0 = 0.f, l1 = 0.f;
    const float qgf   = (float)(wrow + r);

    for (int it = 0; it < T_ / 64; it++) {
        // store current chunk to smem with tf32 rounding
        #pragma unroll
        for (int j = 0; j < 4; j++) {
            float4 kv = kr[j], vv = vr[j];
            float* kd = &Ks[ldrow][ldc + 4 * j];
            kd[0] = __uint_as_float(f2tf(kv.x));
            kd[1] = __uint_as_float(f2tf(kv.y));
            kd[2] = __uint_as_float(f2tf(kv.z));
            kd[3] = __uint_as_float(f2tf(kv.w));
            float* vd = &Vs[ldrow][ldc + 4 * j];
            vd[0] = __uint_as_float(f2tf(vv.x));
            vd[1] = __uint_as_float(f2tf(vv.y));
            vd[2] = __uint_as_float(f2tf(vv.z));
            vd[3] = __uint_as_float(f2tf(vv.w));
        }
        __syncthreads();

        // prefetch next chunk into registers
        if (it + 1 < T_ / 64) {
            const float* kp = kb + (size_t)((it + 1) * 64 + ldrow) * DH_ + ldc;
            const float* vp = vb + (size_t)((it + 1) * 64 + ldrow) * DH_ + ldc;
            #pragma unroll
            for (int j = 0; j < 4; j++) {
                kr[j] = *(const float4*)(kp + 4 * j);
                vr[j] = *(const float4*)(vp + 4 * j);
            }
        }

        // ---- S = Q @ K^T (log2 domain) ----
        float s[8][4];
        #pragma unroll
        for (int ni = 0; ni < 8; ni++) { s[ni][0]=0.f; s[ni][1]=0.f; s[ni][2]=0.f; s[ni][3]=0.f; }
        #pragma unroll
        for (int ni = 0; ni < 8; ni++) {
            #pragma unroll
            for (int kt = 0; kt < 8; kt++) {
                uint32_t b0 = __float_as_uint(Ks[ni * 8 + r][kt * 8 + ql]);
                uint32_t b1 = __float_as_uint(Ks[ni * 8 + r][kt * 8 + ql + 4]);
                asm volatile(
                    "mma.sync.aligned.m16n8k8.row.col.f32.tf32.tf32.f32 "
                    "{%0,%1,%2,%3}, {%4,%5,%6,%7}, {%8,%9}, {%0,%1,%2,%3};"
                    : "+f"(s[ni][0]), "+f"(s[ni][1]), "+f"(s[ni][2]), "+f"(s[ni][3])
                    : "r"(qa[kt][0]), "r"(qa[kt][1]), "r"(qa[kt][2]), "r"(qa[kt][3]),
                      "r"(b0), "r"(b1));
            }
        }

        // ---- ALiBi bias + row max ----
        const float dbase = qgf - (float)(it * 64 + 2 * ql);
        float mx0 = -1e30f, mx1 = -1e30f;
        #pragma unroll
        for (int ni = 0; ni < 8; ni++) {
            float d0 = dbase - (float)(8 * ni);
            s[ni][0] = fmaf(-slope2, fabsf(d0),        s[ni][0]);
            s[ni][1] = fmaf(-slope2, fabsf(d0 - 1.f),  s[ni][1]);
            s[ni][2] = fmaf(-slope2, fabsf(d0 + 8.f),  s[ni][2]);
            s[ni][3] = fmaf(-slope2, fabsf(d0 + 7.f),  s[ni][3]);
            mx0 = fmaxf(mx0, fmaxf(s[ni][0], s[ni][1]));
            mx1 = fmaxf(mx1, fmaxf(s[ni][2], s[ni][3]));
        }
        mx0 = fmaxf(mx0, __shfl_xor_sync(0xffffffffu, mx0, 1));
        mx0 = fmaxf(mx0, __shfl_xor_sync(0xffffffffu, mx0, 2));
        mx1 = fmaxf(mx1, __shfl_xor_sync(0xffffffffu, mx1, 1));
        mx1 = fmaxf(mx1, __shfl_xor_sync(0xffffffffu, mx1, 2));

        float mn0 = fmaxf(m0, mx0), mn1 = fmaxf(m1, mx1);
        float al0 = fexp2(m0 - mn0), al1 = fexp2(m1 - mn1);
        m0 = mn0; m1 = mn1;

        // ---- exp2 + row sums ----
        float rs0 = 0.f, rs1 = 0.f;
        #pragma unroll
        for (int ni = 0; ni < 8; ni++) {
            s[ni][0] = fexp2(s[ni][0] - mn0); rs0 += s[ni][0];
            s[ni][1] = fexp2(s[ni][1] - mn0); rs0 += s[ni][1];
            s[ni][2] = fexp2(s[ni][2] - mn1); rs1 += s[ni][2];
            s[ni][3] = fexp2(s[ni][3] - mn1); rs1 += s[ni][3];
        }
        rs0 += __shfl_xor_sync(0xffffffffu, rs0, 1);
        rs0 += __shfl_xor_sync(0xffffffffu, rs0, 2);
        rs1 += __shfl_xor_sync(0xffffffffu, rs1, 1);
        rs1 += __shfl_xor_sync(0xffffffffu, rs1, 2);
        l0 = l0 * al0 + rs0;
        l1 = l1 * al1 + rs1;

        // rescale O
        #pragma unroll
        for (int no = 0; no < 8; no++) {
            o[no][0] *= al0; o[no][1] *= al0;
            o[no][2] *= al1; o[no][3] *= al1;
        }

        // ---- P layout fixup (accum -> A frag via quad shuffles) + P@V ----
        const int srcA = (lane & ~3) | (ql >> 1);
        const int srcB = srcA | 2;
        #pragma unroll
        for (int kt = 0; kt < 8; kt++) {
            float v0 = __shfl_sync(0xffffffffu, s[kt][0], srcA);
            float v1 = __shfl_sync(0xffffffffu, s[kt][1], srcA);
            float v2 = __shfl_sync(0xffffffffu, s[kt][2], srcA);
            float v3 = __shfl_sync(0xffffffffu, s[kt][3], srcA);
            float w0 = __shfl_sync(0xffffffffu, s[kt][0], srcB);
            float w1 = __shfl_sync(0xffffffffu, s[kt][1], srcB);
            float w2 = __shfl_sync(0xffffffffu, s[kt][2], srcB);
            float w3 = __shfl_sync(0xffffffffu, s[kt][3], srcB);
            uint32_t pa0 = f2tf((lane & 1) ? v1 : v0);
            uint32_t pa1 = f2tf((lane & 1) ? v3 : v2);
            uint32_t pa2 = f2tf((lane & 1) ? w1 : w0);
            uint32_t pa3 = f2tf((lane & 1) ? w3 : w2);
            #pragma unroll
            for (int no = 0; no < 8; no++) {
                uint32_t b0 = __float_as_uint(Vs[kt * 8 + ql][no * 8 + r]);
                uint32_t b1 = __float_as_uint(Vs[kt * 8 + ql + 4][no * 8 + r]);
                asm volatile(
                    "mma.sync.aligned.m16n8k8.row.col.f32.tf32.tf32.f32 "
                    "{%0,%1,%2,%3}, {%4,%5,%6,%7}, {%8,%9}, {%0,%1,%2,%3};"
                    : "+f"(o[no][0]), "+f"(o[no][1]), "+f"(o[no][2]), "+f"(o[no][3])
                    : "r"(pa0), "r"(pa1), "r"(pa2), "r"(pa3),
                      "r"(b0), "r"(b1));
            }
        }
        __syncthreads();
    }

    // ---- epilogue: normalize, tf32-round, write (B, T, H*Dh) ----
    const float inv0 = 1.0f / l0, inv1 = 1.0f / l1;
    const int bb = bh >> 4;
    float* ob0 = out + ((size_t)(bb * T_ + wrow + r)) * D_ + h * DH_;
    float* ob1 = out + ((size_t)(bb * T_ + wrow + r + 8)) * D_ + h * DH_;
    #pragma unroll
    for (int no = 0; no < 8; no++) {
        int c = no * 8 + 2 * ql;
        float2 w0, w1;
        w0.x = __uint_as_float(f2tf(o[no][0] * inv0));
        w0.y = __uint_as_float(f2tf(o[no][1] * inv0));
        w1.x = __uint_as_float(f2tf(o[no][2] * inv1));
        w1.y = __uint_as_float(f2tf(o[no][3] * inv1));
        *(float2*)(ob0 + c) = w0;
        *(float2*)(ob1 + c) = w1;
    }
}

// ---------------------------------------------------------------------------
extern "C" void kernel_launch(void* const* d_in, const int* in_sizes, int n_in,
                              void* d_out, int out_size)
{
    const float* x  = (const float*)d_in[0];
    const float* wq = (const float*)d_in[1];
    const float* wk = (const float*)d_in[2];
    const float* wv = (const float*)d_in[3];
    const float* wv_ = wv;
    const float* wo = (const float*)d_in[4];
    const float* bo = (const float*)d_in[5];
    (void)wv_;

    float *qp, *kp, *vp, *ap, *xp, *wqp, *wkp, *wvp, *wop;
    cudaGetSymbolAddress((void**)&qp,  g_q);
    cudaGetSymbolAddress((void**)&kp,  g_k);
    cudaGetSymbolAddress((void**)&vp,  g_v);
    cudaGetSymbolAddress((void**)&ap,  g_att);
    cudaGetSymbolAddress((void**)&xp,  g_x);
    cudaGetSymbolAddress((void**)&wqp, g_wq);
    cudaGetSymbolAddress((void**)&wkp, g_wk);
    cudaGetSymbolAddress((void**)&wvp, g_wv);
    cudaGetSymbolAddress((void**)&wop, g_wo);

    const int nx4 = M_ * D_ / 4, nw4 = D_ * D_ / 4;
    round_tf32_kernel<<<(nx4 + 255) / 256, 256>>>(x,  xp,  nx4);
    round_tf32_kernel<<<(nw4 + 255) / 256, 256>>>(wq, wqp, nw4);
    round_tf32_kernel<<<(nw4 + 255) / 256, 256>>>(wk, wkp, nw4);
    round_tf32_kernel<<<(nw4 + 255) / 256, 256>>>(wv, wvp, nw4);
    round_tf32_kernel<<<(nw4 + 255) / 256, 256>>>(wo, wop, nw4);

    cudaFuncSetAttribute(gemm_tc<0>,
                         cudaFuncAttributeMaxDynamicSharedMemorySize, GEMM_SMEM);
    cudaFuncSetAttribute(gemm_tc<1>,
                         cudaFuncAttributeMaxDynamicSharedMemorySize, GEMM_SMEM);

    dim3 gg(D_ / 128, M_ / 128);
    gemm_tc<0><<<gg, 256, GEMM_SMEM>>>(xp, wqp, nullptr, qp);
    gemm_tc<0><<<gg, 256, GEMM_SMEM>>>(xp, wkp, nullptr, kp);
    gemm_tc<0><<<gg, 256, GEMM_SMEM>>>(xp, wvp, nullptr, vp);

    attn_tc<<<dim3(T_ / 128, B_ * H_), 256>>>(qp, kp, vp, ap);

    gemm_tc<1><<<gg, 256, GEMM_SMEM>>>(ap, wop, bo, (float*)d_out);
}

// round 8
// speedup vs baseline: 3.2592x; 1.1458x over previous
#include <cuda_runtime.h>
#include <math.h>
#include <stdint.h>

#define B_  4
#define T_  2048
#define D_  1024
#define H_  16
#define DH_ 64
#define M_  (B_ * T_)   // 8192

// Scratch (device globals; no allocation allowed)
__device__ float g_q[B_ * H_ * T_ * DH_];
__device__ float g_k[B_ * H_ * T_ * DH_];
__device__ float g_v[B_ * H_ * T_ * DH_];
__device__ float g_att[M_ * D_];
__device__ float g_x[M_ * D_];
__device__ float g_wq[D_ * D_];
__device__ float g_wk[D_ * D_];
__device__ float g_wv[D_ * D_];
__device__ float g_wo[D_ * D_];

#define QSC 0.1803368801111154f   /* 0.125 * log2(e), folded into K */

__device__ __forceinline__ uint32_t f2tf(float f) {
    uint32_t u;
    asm("cvt.rna.tf32.f32 %0, %1;" : "=r"(u) : "f"(f));
    return u;
}

// fast 2^t on the FMA pipe (no MUFU). |err| ~2e-6 rel.
__device__ __forceinline__ float fexp2(float t) {
    t = fmaxf(t, -126.0f);
    float nf = t + 12582912.0f;
    float f  = t - (nf - 12582912.0f);
    float p  = 0.0013333558f;
    p = fmaf(p, f, 0.0096181291f);
    p = fmaf(p, f, 0.0555041087f);
    p = fmaf(p, f, 0.2402265070f);
    p = fmaf(p, f, 0.6931471806f);
    p = fmaf(p, f, 1.0f);
    return __int_as_float(__float_as_int(p) + (__float_as_int(nf) << 23));
}

// ---------------------------------------------------------------------------
__global__ void round_tf32_kernel(const float* __restrict__ in,
                                  float* __restrict__ out, int n4)
{
    int i = blockIdx.x * blockDim.x + threadIdx.x;
    if (i < n4) {
        float4 v = ((const float4*)in)[i];
        v.x = __uint_as_float(f2tf(v.x));
        v.y = __uint_as_float(f2tf(v.y));
        v.z = __uint_as_float(f2tf(v.z));
        v.w = __uint_as_float(f2tf(v.w));
        ((float4*)out)[i] = v;
    }
}

// ---------------------------------------------------------------------------
// Tensor-core tf32 GEMM (legacy mma.sync, proven): C = A(MxK) @ W^T.
// MODE 0: scatter into (B,H,T,Dh), output scaled by `scale` and tf32-rounded.
// MODE 1: linear + bias (raw fp32 out).
// ---------------------------------------------------------------------------
#define SA 36
#define TILE_U32 (128 * SA)
#define GEMM_SMEM (2 * 2 * TILE_U32 * 4)

template <int MODE>
__global__ void __launch_bounds__(256, 2) gemm_tc(
    const float* __restrict__ A, const float* __restrict__ W,
    const float* __restrict__ bias, float* __restrict__ C, float scale)
{
    constexpr int K = 1024;
    extern __shared__ uint32_t sm[];

    const int tid  = threadIdx.x;
    const int lane = tid & 31;
    const int warp = tid >> 5;
    const int wm   = warp & 3;
    const int wn   = warp >> 2;
    const int m0   = blockIdx.y * 128;
    const int n0   = blockIdx.x * 128;

    const int k4   = (tid & 7) * 4;
    const int mrow = tid >> 3;

    auto load_tile = [&](int k0, int s) {
        uint32_t* As = sm + s * 2 * TILE_U32;
        uint32_t* Bs = As + TILE_U32;
        #pragma unroll
        for (int t = 0; t < 4; t++) {
            int m = mrow + t * 32;
            const float* ga = A + (size_t)(m0 + m) * K + k0 + k4;
            unsigned sa = (unsigned)__cvta_generic_to_shared(&As[m * SA + k4]);
            asm volatile("cp.async.cg.shared.global [%0], [%1], 16;" :: "r"(sa), "l"(ga));
            const float* gb = W + (size_t)(n0 + m) * K + k0 + k4;
            unsigned sb = (unsigned)__cvta_generic_to_shared(&Bs[m * SA + k4]);
            asm volatile("cp.async.cg.shared.global [%0], [%1], 16;" :: "r"(sb), "l"(gb));
        }
        asm volatile("cp.async.commit_group;");
    };

    float c[2][8][4] = {};
    load_tile(0, 0);

    const int r    = lane >> 2;
    const int csel = lane & 3;

    for (int it = 0; it < K / 32; ++it) {
        if (it + 1 < K / 32) {
            load_tile((it + 1) * 32, (it + 1) & 1);
            asm volatile("cp.async.wait_group 1;");
        } else {
            asm volatile("cp.async.wait_group 0;");
        }
        __syncthreads();

        const uint32_t* As = sm + (it & 1) * 2 * TILE_U32;
        const uint32_t* Bs = As + TILE_U32;

        #pragma unroll
        for (int kk = 0; kk < 32; kk += 8) {
            uint32_t a[2][4], b[8][2];
            #pragma unroll
            for (int mi = 0; mi < 2; mi++) {
                const uint32_t* p = As + (wm * 32 + mi * 16 + r) * SA + kk + csel;
                a[mi][0] = p[0];
                a[mi][2] = p[4];
                a[mi][1] = p[8 * SA];
                a[mi][3] = p[8 * SA + 4];
            }
            #pragma unroll
            for (int ni = 0; ni < 8; ni++) {
                const uint32_t* p = Bs + (wn * 64 + ni * 8 + r) * SA + kk + csel;
                b[ni][0] = p[0];
                b[ni][1] = p[4];
            }
            #pragma unroll
            for (int mi = 0; mi < 2; mi++)
                #pragma unroll
                for (int ni = 0; ni < 8; ni++)
                    asm volatile(
                        "mma.sync.aligned.m16n8k8.row.col.f32.tf32.tf32.f32 "
                        "{%0,%1,%2,%3}, {%4,%5,%6,%7}, {%8,%9}, {%0,%1,%2,%3};"
                        : "+f"(c[mi][ni][0]), "+f"(c[mi][ni][1]),
                          "+f"(c[mi][ni][2]), "+f"(c[mi][ni][3])
                        : "r"(a[mi][0]), "r"(a[mi][1]), "r"(a[mi][2]), "r"(a[mi][3]),
                          "r"(b[ni][0]), "r"(b[ni][1]));
        }
        __syncthreads();
    }

    const int cq = (lane & 3) * 2;
    #pragma unroll
    for (int mi = 0; mi < 2; mi++) {
        #pragma unroll
        for (int ni = 0; ni < 8; ni++) {
            int n = n0 + wn * 64 + ni * 8 + cq;
            #pragma unroll
            for (int half = 0; half < 2; half++) {
                int m = m0 + wm * 32 + mi * 16 + r + half * 8;
                if (MODE == 0) {
                    // tf32-round (+scale) so attention consumes raw bits
                    float2 vo;
                    vo.x = __uint_as_float(f2tf(c[mi][ni][half * 2]     * scale));
                    vo.y = __uint_as_float(f2tf(c[mi][ni][half * 2 + 1] * scale));
                    int h = n >> 6, d = n & 63;
                    int bb = m >> 11, t = m & 2047;
                    *(float2*)(C + ((size_t)((bb << 4) + h) * T_ + t) * DH_ + d) = vo;
                } else {
                    float2 b2 = *(const float2*)(bias + n);
                    float2 vo = make_float2(c[mi][ni][half * 2]     + b2.x,
                                            c[mi][ni][half * 2 + 1] + b2.y);
                    *(float2*)(C + (size_t)m * D_ + n) = vo;
                }
            }
        }
    }
}

// ---------------------------------------------------------------------------
// Tensor-core flash attention, ALiBi, log2-domain softmax, poly exp2.
// Inputs pre-rounded to tf32 (K pre-scaled by QSC) by the GEMM epilogue.
// K/V staged via cp.async double-buffered smem.
// grid (T/128, B*H), 256 threads = 8 warps; warp w owns q-rows [w*16, w*16+16).
// ---------------------------------------------------------------------------
#define KV_STRIDE (64 * 68 + 64 * 72)          // floats per stage
#define ATTN_SMEM (2 * KV_STRIDE * 4)          // 71680 bytes

__global__ void __launch_bounds__(256) attn_tc(
    const float* __restrict__ q, const float* __restrict__ k,
    const float* __restrict__ v, float* __restrict__ out)
{
    extern __shared__ float smd[];

    const int tid  = threadIdx.x;
    const int lane = tid & 31;
    const int warp = tid >> 5;
    const int q0   = blockIdx.x * 128;
    const int bh   = blockIdx.y;
    const int h    = bh & (H_ - 1);
    const float slope2 = exp2f(-0.5f * (float)(h + 1)) * 1.4426950408889634f;

    const float* qb = q + (size_t)bh * T_ * DH_;
    const float* kb = k + (size_t)bh * T_ * DH_;
    const float* vb = v + (size_t)bh * T_ * DH_;

    const int r    = lane >> 2;       // 0..7
    const int ql   = lane & 3;        // 0..3
    const int wrow = q0 + warp * 16;

    // ---- Q fragments: raw loads (already tf32-grid; scale folded into K) --
    uint32_t qa[8][4];
    #pragma unroll
    for (int kt = 0; kt < 8; kt++) {
        const uint32_t* p0 = (const uint32_t*)(qb + (size_t)(wrow + r) * DH_) + kt * 8 + ql;
        qa[kt][0] = p0[0];
        qa[kt][2] = p0[4];
        qa[kt][1] = p0[8 * DH_];
        qa[kt][3] = p0[8 * DH_ + 4];
    }

    // ---- cp.async K/V loader --------------------------------------------
    const int ldrow = tid >> 2;          // 0..63
    const int ldc   = (tid & 3) * 16;    // 0,16,32,48

    auto load_kv = [&](int it, int s) {
        float* Kd = smd + s * KV_STRIDE;
        float* Vd = Kd + 64 * 68;
        const float* kp = kb + (size_t)(it * 64 + ldrow) * DH_ + ldc;
        const float* vp = vb + (size_t)(it * 64 + ldrow) * DH_ + ldc;
        #pragma unroll
        for (int j = 0; j < 4; j++) {
            unsigned dk = (unsigned)__cvta_generic_to_shared(&Kd[ldrow * 68 + ldc + 4 * j]);
            asm volatile("cp.async.cg.shared.global [%0], [%1], 16;" :: "r"(dk), "l"(kp + 4 * j));
            unsigned dv = (unsigned)__cvta_generic_to_shared(&Vd[ldrow * 72 + ldc + 4 * j]);
            asm volatile("cp.async.cg.shared.global [%0], [%1], 16;" :: "r"(dv), "l"(vp + 4 * j));
        }
        asm volatile("cp.async.commit_group;");
    };

    float o[8][4] = {};
    float m0 = -1e30f, m1 = -1e30f, l0 = 0.f, l1 = 0.f;
    const float qgf = (float)(wrow + r);

    load_kv(0, 0);

    for (int it = 0; it < T_ / 64; it++) {
        if (it + 1 < T_ / 64) {
            load_kv(it + 1, (it + 1) & 1);
            asm volatile("cp.async.wait_group 1;");
        } else {
            asm volatile("cp.async.wait_group 0;");
        }
        __syncthreads();

        const float* Ksb = smd + (it & 1) * KV_STRIDE;
        const float* Vsb = Ksb + 64 * 68;

        // ---- S = Q @ K^T (log2 domain; QSC folded into K) ----
        float s[8][4];
        #pragma unroll
        for (int ni = 0; ni < 8; ni++) { s[ni][0]=0.f; s[ni][1]=0.f; s[ni][2]=0.f; s[ni][3]=0.f; }
        #pragma unroll
        for (int ni = 0; ni < 8; ni++) {
            #pragma unroll
            for (int kt = 0; kt < 8; kt++) {
                uint32_t b0 = __float_as_uint(Ksb[(ni * 8 + r) * 68 + kt * 8 + ql]);
                uint32_t b1 = __float_as_uint(Ksb[(ni * 8 + r) * 68 + kt * 8 + ql + 4]);
                asm volatile(
                    "mma.sync.aligned.m16n8k8.row.col.f32.tf32.tf32.f32 "
                    "{%0,%1,%2,%3}, {%4,%5,%6,%7}, {%8,%9}, {%0,%1,%2,%3};"
                    : "+f"(s[ni][0]), "+f"(s[ni][1]), "+f"(s[ni][2]), "+f"(s[ni][3])
                    : "r"(qa[kt][0]), "r"(qa[kt][1]), "r"(qa[kt][2]), "r"(qa[kt][3]),
                      "r"(b0), "r"(b1));
            }
        }

        // ---- ALiBi bias + row max ----
        const float dbase = qgf - (float)(it * 64 + 2 * ql);
        float mx0 = -1e30f, mx1 = -1e30f;
        #pragma unroll
        for (int ni = 0; ni < 8; ni++) {
            float d0 = dbase - (float)(8 * ni);
            s[ni][0] = fmaf(-slope2, fabsf(d0),        s[ni][0]);
            s[ni][1] = fmaf(-slope2, fabsf(d0 - 1.f),  s[ni][1]);
            s[ni][2] = fmaf(-slope2, fabsf(d0 + 8.f),  s[ni][2]);
            s[ni][3] = fmaf(-slope2, fabsf(d0 + 7.f),  s[ni][3]);
            mx0 = fmaxf(mx0, fmaxf(s[ni][0], s[ni][1]));
            mx1 = fmaxf(mx1, fmaxf(s[ni][2], s[ni][3]));
        }
        mx0 = fmaxf(mx0, __shfl_xor_sync(0xffffffffu, mx0, 1));
        mx0 = fmaxf(mx0, __shfl_xor_sync(0xffffffffu, mx0, 2));
        mx1 = fmaxf(mx1, __shfl_xor_sync(0xffffffffu, mx1, 1));
        mx1 = fmaxf(mx1, __shfl_xor_sync(0xffffffffu, mx1, 2));

        float mn0 = fmaxf(m0, mx0), mn1 = fmaxf(m1, mx1);
        float al0 = fexp2(m0 - mn0), al1 = fexp2(m1 - mn1);
        m0 = mn0; m1 = mn1;

        // ---- exp2 + row sums ----
        float rs0 = 0.f, rs1 = 0.f;
        #pragma unroll
        for (int ni = 0; ni < 8; ni++) {
            s[ni][0] = fexp2(s[ni][0] - mn0); rs0 += s[ni][0];
            s[ni][1] = fexp2(s[ni][1] - mn0); rs0 += s[ni][1];
            s[ni][2] = fexp2(s[ni][2] - mn1); rs1 += s[ni][2];
            s[ni][3] = fexp2(s[ni][3] - mn1); rs1 += s[ni][3];
        }
        rs0 += __shfl_xor_sync(0xffffffffu, rs0, 1);
        rs0 += __shfl_xor_sync(0xffffffffu, rs0, 2);
        rs1 += __shfl_xor_sync(0xffffffffu, rs1, 1);
        rs1 += __shfl_xor_sync(0xffffffffu, rs1, 2);
        l0 = l0 * al0 + rs0;
        l1 = l1 * al1 + rs1;

        #pragma unroll
        for (int no = 0; no < 8; no++) {
            o[no][0] *= al0; o[no][1] *= al0;
            o[no][2] *= al1; o[no][3] *= al1;
        }

        // ---- P layout fixup (accum -> A frag via quad shuffles) + P@V ----
        const int srcA = (lane & ~3) | (ql >> 1);
        const int srcB = srcA | 2;
        #pragma unroll
        for (int kt = 0; kt < 8; kt++) {
            float v0 = __shfl_sync(0xffffffffu, s[kt][0], srcA);
            float v1 = __shfl_sync(0xffffffffu, s[kt][1], srcA);
            float v2 = __shfl_sync(0xffffffffu, s[kt][2], srcA);
            float v3 = __shfl_sync(0xffffffffu, s[kt][3], srcA);
            float w0 = __shfl_sync(0xffffffffu, s[kt][0], srcB);
            float w1 = __shfl_sync(0xffffffffu, s[kt][1], srcB);
            float w2 = __shfl_sync(0xffffffffu, s[kt][2], srcB);
            float w3 = __shfl_sync(0xffffffffu, s[kt][3], srcB);
            uint32_t pa0 = f2tf((lane & 1) ? v1 : v0);
            uint32_t pa1 = f2tf((lane & 1) ? v3 : v2);
            uint32_t pa2 = f2tf((lane & 1) ? w1 : w0);
            uint32_t pa3 = f2tf((lane & 1) ? w3 : w2);
            #pragma unroll
            for (int no = 0; no < 8; no++) {
                uint32_t b0 = __float_as_uint(Vsb[(kt * 8 + ql) * 72 + no * 8 + r]);
                uint32_t b1 = __float_as_uint(Vsb[(kt * 8 + ql + 4) * 72 + no * 8 + r]);
                asm volatile(
                    "mma.sync.aligned.m16n8k8.row.col.f32.tf32.tf32.f32 "
                    "{%0,%1,%2,%3}, {%4,%5,%6,%7}, {%8,%9}, {%0,%1,%2,%3};"
                    : "+f"(o[no][0]), "+f"(o[no][1]), "+f"(o[no][2]), "+f"(o[no][3])
                    : "r"(pa0), "r"(pa1), "r"(pa2), "r"(pa3),
                      "r"(b0), "r"(b1));
            }
        }
        __syncthreads();
    }

    // ---- epilogue: normalize, tf32-round, write (B, T, H*Dh) ----
    const float inv0 = 1.0f / l0, inv1 = 1.0f / l1;
    const int bb = bh >> 4;
    float* ob0 = out + ((size_t)(bb * T_ + wrow + r)) * D_ + h * DH_;
    float* ob1 = out + ((size_t)(bb * T_ + wrow + r + 8)) * D_ + h * DH_;
    #pragma unroll
    for (int no = 0; no < 8; no++) {
        int c = no * 8 + 2 * ql;
        float2 w0, w1;
        w0.x = __uint_as_float(f2tf(o[no][0] * inv0));
        w0.y = __uint_as_float(f2tf(o[no][1] * inv0));
        w1.x = __uint_as_float(f2tf(o[no][2] * inv1));
        w1.y = __uint_as_float(f2tf(o[no][3] * inv1));
        *(float2*)(ob0 + c) = w0;
        *(float2*)(ob1 + c) = w1;
    }
}

// ---------------------------------------------------------------------------
extern "C" void kernel_launch(void* const* d_in, const int* in_sizes, int n_in,
                              void* d_out, int out_size)
{
    const float* x  = (const float*)d_in[0];
    const float* wq = (const float*)d_in[1];
    const float* wk = (const float*)d_in[2];
    const float* wv = (const float*)d_in[3];
    const float* wo = (const float*)d_in[4];
    const float* bo = (const float*)d_in[5];

    float *qp, *kp, *vp, *ap, *xp, *wqp, *wkp, *wvp, *wop;
    cudaGetSymbolAddress((void**)&qp,  g_q);
    cudaGetSymbolAddress((void**)&kp,  g_k);
    cudaGetSymbolAddress((void**)&vp,  g_v);
    cudaGetSymbolAddress((void**)&ap,  g_att);
    cudaGetSymbolAddress((void**)&xp,  g_x);
    cudaGetSymbolAddress((void**)&wqp, g_wq);
    cudaGetSymbolAddress((void**)&wkp, g_wk);
    cudaGetSymbolAddress((void**)&wvp, g_wv);
    cudaGetSymbolAddress((void**)&wop, g_wo);

    const int nx4 = M_ * D_ / 4, nw4 = D_ * D_ / 4;
    round_tf32_kernel<<<(nx4 + 255) / 256, 256>>>(x,  xp,  nx4);
    round_tf32_kernel<<<(nw4 + 255) / 256, 256>>>(wq, wqp, nw4);
    round_tf32_kernel<<<(nw4 + 255) / 256, 256>>>(wk, wkp, nw4);
    round_tf32_kernel<<<(nw4 + 255) / 256, 256>>>(wv, wvp, nw4);
    round_tf32_kernel<<<(nw4 + 255) / 256, 256>>>(wo, wop, nw4);

    cudaFuncSetAttribute(gemm_tc<0>,
                         cudaFuncAttributeMaxDynamicSharedMemorySize, GEMM_SMEM);
    cudaFuncSetAttribute(gemm_tc<1>,
                         cudaFuncAttributeMaxDynamicSharedMemorySize, GEMM_SMEM);

    dim3 gg(D_ / 128, M_ / 128);   // (8, 64)
    gemm_tc<0><<<gg, 256, GEMM_SMEM>>>(xp, wqp, nullptr, qp, 1.0f);
    gemm_tc<0><<<gg, 256, GEMM_SMEM>>>(xp, wkp, nullptr, kp, QSC);   // fold scale into K
    gemm_tc<0><<<gg, 256, GEMM_SMEM>>>(xp, wvp, nullptr, vp, 1.0f);

    cudaFuncSetAttribute(attn_tc,
                         cudaFuncAttributeMaxDynamicSharedMemorySize, ATTN_SMEM);
    attn_tc<<<dim3(T_ / 128, B_ * H_), 256, ATTN_SMEM>>>(qp, kp, vp, ap);

    gemm_tc<1><<<gg, 256, GEMM_SMEM>>>(ap, wop, bo, (float*)d_out, 1.0f);
}

// round 11
// speedup vs baseline: 6.7184x; 2.0614x over previous
#include <cuda_runtime.h>
#include <cuda_fp16.h>
#include <math.h>
#include <stdint.h>

#define B_  4
#define T_  2048
#define D_  1024
#define H_  16
#define DH_ 64
#define M_  (B_ * T_)   // 8192

#define QSC 0.1803368801111154f   /* 0.125 * log2(e), folded into K */

// Scratch (device globals; no allocation allowed)
__device__ __half g_q[B_ * H_ * T_ * DH_];
__device__ __half g_k[B_ * H_ * T_ * DH_];
__device__ __half g_vt[B_ * H_ * DH_ * T_];   // V transposed (B,H,Dh,T)
__device__ __half g_att[M_ * D_];
__device__ __half g_x[M_ * D_];
__device__ __half g_wq[D_ * D_];
__device__ __half g_wk[D_ * D_];
__device__ __half g_wv[D_ * D_];
__device__ __half g_wo[D_ * D_];

// fast 2^t on the FMA pipe (no MUFU). |err| ~2e-6 rel.
__device__ __forceinline__ float fexp2(float t) {
    t = fmaxf(t, -126.0f);
    float nf = t + 12582912.0f;
    float f  = t - (nf - 12582912.0f);
    float p  = 0.0013333558f;
    p = fmaf(p, f, 0.0096181291f);
    p = fmaf(p, f, 0.0555041087f);
    p = fmaf(p, f, 0.2402265070f);
    p = fmaf(p, f, 0.6931471806f);
    p = fmaf(p, f, 1.0f);
    return __int_as_float(__float_as_int(p) + (__float_as_int(nf) << 23));
}

__device__ __forceinline__ void ldsm4(uint32_t& r0, uint32_t& r1,
                                      uint32_t& r2, uint32_t& r3, uint32_t addr) {
    asm volatile("ldmatrix.sync.aligned.m8n8.x4.shared.b16 {%0,%1,%2,%3}, [%4];"
                 : "=r"(r0), "=r"(r1), "=r"(r2), "=r"(r3) : "r"(addr));
}

#define MMA16(c, a0, a1, a2, a3, b0, b1) \
    asm volatile( \
        "mma.sync.aligned.m16n8k16.row.col.f32.f16.f16.f32 " \
        "{%0,%1,%2,%3}, {%4,%5,%6,%7}, {%8,%9}, {%0,%1,%2,%3};" \
        : "+f"((c)[0]), "+f"((c)[1]), "+f"((c)[2]), "+f"((c)[3]) \
        : "r"(a0), "r"(a1), "r"(a2), "r"(a3), "r"(b0), "r"(b1))

// pack two floats into one f16x2 register (single cvt instruction)
__device__ __forceinline__ uint32_t packh2(float a, float b) {
    uint32_t u;
    asm("cvt.rn.f16x2.f32 %0, %2, %1;" : "=r"(u) : "f"(a), "f"(b));
    return u;   // lo = a, hi = b
}

// ---------------------------------------------------------------------------
// float -> half conversion pre-pass
// ---------------------------------------------------------------------------
__global__ void f2h_kernel(const float* __restrict__ in,
                           __half* __restrict__ out, int n4)
{
    int i = blockIdx.x * blockDim.x + threadIdx.x;
    if (i < n4) {
        float4 v = ((const float4*)in)[i];
        uint2 o;
        o.x = packh2(v.x, v.y);
        o.y = packh2(v.z, v.w);
        ((uint2*)out)[i] = o;
    }
}

// ---------------------------------------------------------------------------
// fp16 tensor-core GEMM: C = A(MxK) @ W^T, W (N x K) row-major, K = 1024.
// BM=BN=128, BK=64 (128B fp16 rows). 8 warps (4m x 2n), warp tile 32x64.
// MODE 0: half out, scatter (B,H,T,Dh), scaled.  MODE 2: half out, scatter
// transposed (B,H,Dh,T), scaled.  MODE 1: float out + bias.
// ---------------------------------------------------------------------------
#define GSTR  72                 // halves per smem row (144B, LDSM conflict-free)
#define GTILE (128 * GSTR)       // halves per matrix tile
#define GEMM_SMEM (4 * GTILE * 2)  // 73728 bytes

template <int MODE>
__global__ void __launch_bounds__(256, 2) gemm_h(
    const __half* __restrict__ A, const __half* __restrict__ W,
    const float* __restrict__ bias, void* __restrict__ Cout, float scale)
{
    constexpr int K = 1024, NT = K / 64;
    extern __shared__ __align__(16) __half smh[];
    const uint32_t sb = (uint32_t)__cvta_generic_to_shared(smh);

    const int tid  = threadIdx.x;
    const int lane = tid & 31;
    const int warp = tid >> 5;
    const int wm   = warp & 3;
    const int wn   = warp >> 2;
    const int m0   = blockIdx.y * 128;
    const int n0   = blockIdx.x * 128;

    const int c16  = tid & 7;        // 16B chunk (8 halves)
    const int row0 = tid >> 3;       // 0..31

    auto load_tile = [&](int it, int s) {
        uint32_t base = sb + (uint32_t)s * (2 * GTILE * 2);
        #pragma unroll
        for (int rep = 0; rep < 4; rep++) {
            int rr = row0 + rep * 32;
            uint32_t d = base + (uint32_t)rr * (GSTR * 2) + (uint32_t)c16 * 16;
            const __half* ga = A + (size_t)(m0 + rr) * K + it * 64 + c16 * 8;
            asm volatile("cp.async.cg.shared.global [%0], [%1], 16;" :: "r"(d), "l"(ga));
            const __half* gw = W + (size_t)(n0 + rr) * K + it * 64 + c16 * 8;
            asm volatile("cp.async.cg.shared.global [%0], [%1], 16;"
                         :: "r"(d + GTILE * 2), "l"(gw));
        }
        asm volatile("cp.async.commit_group;");
    };

    float c[2][8][4] = {};
    load_tile(0, 0);

    for (int it = 0; it < NT; ++it) {
        if (it + 1 < NT) {
            load_tile(it + 1, (it + 1) & 1);
            asm volatile("cp.async.wait_group 1;");
        } else {
            asm volatile("cp.async.wait_group 0;");
        }
        __syncthreads();

        uint32_t sbA = sb + (uint32_t)(it & 1) * (2 * GTILE * 2);
        uint32_t sbB = sbA + GTILE * 2;

        #pragma unroll
        for (int kt = 0; kt < 4; kt++) {
            // A fragments: 2 LDSM.x4
            uint32_t a[2][4];
            #pragma unroll
            for (int mi = 0; mi < 2; mi++) {
                int rrow = wm * 32 + mi * 16 + ((lane >> 3) & 1) * 8 + (lane & 7);
                int ccol = kt * 16 + (lane >> 4) * 8;
                ldsm4(a[mi][0], a[mi][1], a[mi][2], a[mi][3],
                      sbA + (uint32_t)(rrow * GSTR + ccol) * 2);
            }
            // B fragments: 4 LDSM.x4 (each covers 2 n-tiles)
            uint32_t b[4][4];
            #pragma unroll
            for (int np = 0; np < 4; np++) {
                int rrow = wn * 64 + np * 16 + (lane >> 4) * 8 + (lane & 7);
                int ccol = kt * 16 + ((lane >> 3) & 1) * 8;
                ldsm4(b[np][0], b[np][1], b[np][2], b[np][3],
                      sbB + (uint32_t)(rrow * GSTR + ccol) * 2);
            }
            #pragma unroll
            for (int mi = 0; mi < 2; mi++)
                #pragma unroll
                for (int np = 0; np < 4; np++) {
                    MMA16(c[mi][2 * np],     a[mi][0], a[mi][1], a[mi][2], a[mi][3],
                          b[np][0], b[np][1]);
                    MMA16(c[mi][2 * np + 1], a[mi][0], a[mi][1], a[mi][2], a[mi][3],
                          b[np][2], b[np][3]);
                }
        }
        __syncthreads();
    }

    const int r  = lane >> 2;
    const int cq = (lane & 3) * 2;
    #pragma unroll
    for (int mi = 0; mi < 2; mi++) {
        #pragma unroll
        for (int ni = 0; ni < 8; ni++) {
            int n = n0 + wn * 64 + ni * 8 + cq;
            #pragma unroll
            for (int half_ = 0; half_ < 2; half_++) {
                int m = m0 + wm * 32 + mi * 16 + r + half_ * 8;
                float v0 = c[mi][ni][half_ * 2], v1 = c[mi][ni][half_ * 2 + 1];
                if (MODE == 0) {
                    __half* C = (__half*)Cout;
                    int h = n >> 6, d = n & 63;
                    int bb = m >> 11, t = m & 2047;
                    uint32_t hv = packh2(v0 * scale, v1 * scale);
                    *(uint32_t*)(C + ((size_t)((bb << 4) + h) * T_ + t) * DH_ + d) = hv;
                } else if (MODE == 2) {
                    __half* C = (__half*)Cout;
                    int h = n >> 6, d = n & 63;
                    int bb = m >> 11, t = m & 2047;
                    size_t base = ((size_t)((bb << 4) + h) * DH_ + d) * T_ + t;
                    C[base]      = __float2half_rn(v0 * scale);
                    C[base + T_] = __float2half_rn(v1 * scale);
                } else {
                    float* C = (float*)Cout;
                    float2 b2 = *(const float2*)(bias + n);
                    *(float2*)(C + (size_t)m * D_ + n) = make_float2(v0 + b2.x, v1 + b2.y);
                }
            }
        }
    }
}

// ---------------------------------------------------------------------------
// fp16 flash attention with ALiBi, log2-domain softmax, poly exp2.
// Q/K half (B,H,T,64), K pre-scaled by QSC; V half transposed (B,H,64,T).
// grid (T/128, B*H), 256 thr = 8 warps; warp w owns q-rows [w*16, w*16+16).
// ---------------------------------------------------------------------------
#define ASTR 72   // halves per smem row

__global__ void __launch_bounds__(256) attn_h(
    const __half* __restrict__ q, const __half* __restrict__ k,
    const __half* __restrict__ vt, __half* __restrict__ out)
{
    __shared__ __align__(16) __half Ksh[2][64 * ASTR];
    __shared__ __align__(16) __half Vsh[2][64 * ASTR];

    const int tid  = threadIdx.x;
    const int lane = tid & 31;
    const int warp = tid >> 5;
    const int q0   = blockIdx.x * 128;
    const int bh   = blockIdx.y;
    const int h    = bh & (H_ - 1);
    const float slope2 = exp2f(-0.5f * (float)(h + 1)) * 1.4426950408889634f;

    const __half* qb  = q  + (size_t)bh * T_ * DH_;
    const __half* kb  = k  + (size_t)bh * T_ * DH_;
    const __half* vtb = vt + (size_t)bh * DH_ * T_;

    const int r    = lane >> 2;       // 0..7
    const int ql   = lane & 3;        // 0..3
    const int wrow = q0 + warp * 16;

    // ---- Q fragments (m16n8k16 A): 16 regs total ----
    uint32_t qa[4][4];
    {
        const uint32_t* q0p = (const uint32_t*)(qb + (size_t)(wrow + r) * DH_);
        const uint32_t* q1p = (const uint32_t*)(qb + (size_t)(wrow + r + 8) * DH_);
        #pragma unroll
        for (int kt = 0; kt < 4; kt++) {
            qa[kt][0] = q0p[kt * 8 + ql];
            qa[kt][1] = q1p[kt * 8 + ql];
            qa[kt][2] = q0p[kt * 8 + ql + 4];
            qa[kt][3] = q1p[kt * 8 + ql + 4];
        }
    }

    const uint32_t ksb = (uint32_t)__cvta_generic_to_shared(&Ksh[0][0]);
    const uint32_t vsb = (uint32_t)__cvta_generic_to_shared(&Vsh[0][0]);

    const int row0 = tid >> 3;       // 0..31
    const int c16  = tid & 7;

    auto load_kv = [&](int it, int s) {
        #pragma unroll
        for (int rep = 0; rep < 2; rep++) {
            int rr = row0 + rep * 32;
            uint32_t dk = ksb + (uint32_t)(s * 64 * ASTR + rr * ASTR) * 2 + (uint32_t)c16 * 16;
            const __half* kp = kb + (size_t)(it * 64 + rr) * DH_ + c16 * 8;
            asm volatile("cp.async.cg.shared.global [%0], [%1], 16;" :: "r"(dk), "l"(kp));
            uint32_t dv = vsb + (uint32_t)(s * 64 * ASTR + rr * ASTR) * 2 + (uint32_t)c16 * 16;
            const __half* vp = vtb + (size_t)rr * T_ + it * 64 + c16 * 8;
            asm volatile("cp.async.cg.shared.global [%0], [%1], 16;" :: "r"(dv), "l"(vp));
        }
        asm volatile("cp.async.commit_group;");
    };

    float o[8][4] = {};
    float m0 = -1e30f, m1 = -1e30f, l0 = 0.f, l1 = 0.f;
    const float qgf = (float)(wrow + r);

    load_kv(0, 0);

    for (int it = 0; it < T_ / 64; it++) {
        if (it + 1 < T_ / 64) {
            load_kv(it + 1, (it + 1) & 1);
            asm volatile("cp.async.wait_group 1;");
        } else {
            asm volatile("cp.async.wait_group 0;");
        }
        __syncthreads();

        const uint32_t kbase = ksb + (uint32_t)((it & 1) * 64 * ASTR) * 2;
        const uint32_t vbase = vsb + (uint32_t)((it & 1) * 64 * ASTR) * 2;

        // ---- S = Q @ K^T (log2 domain; QSC folded into K) ----
        float s[8][4] = {};
        #pragma unroll
        for (int kt = 0; kt < 4; kt++) {
            #pragma unroll
            for (int np = 0; np < 4; np++) {
                int rrow = np * 16 + (lane >> 4) * 8 + (lane & 7);
                int ccol = kt * 16 + ((lane >> 3) & 1) * 8;
                uint32_t b0, b1, b2, b3;
                ldsm4(b0, b1, b2, b3, kbase + (uint32_t)(rrow * ASTR + ccol) * 2);
                MMA16(s[2 * np],     qa[kt][0], qa[kt][1], qa[kt][2], qa[kt][3], b0, b1);
                MMA16(s[2 * np + 1], qa[kt][0], qa[kt][1], qa[kt][2], qa[kt][3], b2, b3);
            }
        }

        // ---- ALiBi bias + row max ----
        const float dbase = qgf - (float)(it * 64 + 2 * ql);
        float mx0 = -1e30f, mx1 = -1e30f;
        #pragma unroll
        for (int ni = 0; ni < 8; ni++) {
            float d0 = dbase - (float)(8 * ni);
            s[ni][0] = fmaf(-slope2, fabsf(d0),       s[ni][0]);
            s[ni][1] = fmaf(-slope2, fabsf(d0 - 1.f), s[ni][1]);
            s[ni][2] = fmaf(-slope2, fabsf(d0 + 8.f), s[ni][2]);
            s[ni][3] = fmaf(-slope2, fabsf(d0 + 7.f), s[ni][3]);
            mx0 = fmaxf(mx0, fmaxf(s[ni][0], s[ni][1]));
            mx1 = fmaxf(mx1, fmaxf(s[ni][2], s[ni][3]));
        }
        mx0 = fmaxf(mx0, __shfl_xor_sync(0xffffffffu, mx0, 1));
        mx0 = fmaxf(mx0, __shfl_xor_sync(0xffffffffu, mx0, 2));
        mx1 = fmaxf(mx1, __shfl_xor_sync(0xffffffffu, mx1, 1));
        mx1 = fmaxf(mx1, __shfl_xor_sync(0xffffffffu, mx1, 2));

        float mn0 = fmaxf(m0, mx0), mn1 = fmaxf(m1, mx1);
        float al0 = fexp2(m0 - mn0), al1 = fexp2(m1 - mn1);
        m0 = mn0; m1 = mn1;

        // ---- exp2 + row sums ----
        float rs0 = 0.f, rs1 = 0.f;
        #pragma unroll
        for (int ni = 0; ni < 8; ni++) {
            s[ni][0] = fexp2(s[ni][0] - mn0); rs0 += s[ni][0];
            s[ni][1] = fexp2(s[ni][1] - mn0); rs0 += s[ni][1];
            s[ni][2] = fexp2(s[ni][2] - mn1); rs1 += s[ni][2];
            s[ni][3] = fexp2(s[ni][3] - mn1); rs1 += s[ni][3];
        }
        rs0 += __shfl_xor_sync(0xffffffffu, rs0, 1);
        rs0 += __shfl_xor_sync(0xffffffffu, rs0, 2);
        rs1 += __shfl_xor_sync(0xffffffffu, rs1, 1);
        rs1 += __shfl_xor_sync(0xffffffffu, rs1, 2);
        l0 = l0 * al0 + rs0;
        l1 = l1 * al1 + rs1;

        #pragma unroll
        for (int no = 0; no < 8; no++) {
            o[no][0] *= al0; o[no][1] *= al0;
            o[no][2] *= al1; o[no][3] *= al1;
        }

        // ---- P@V: pack P accum -> fp16 A frags directly (no shuffles) ----
        #pragma unroll
        for (int kt2 = 0; kt2 < 4; kt2++) {
            uint32_t pa0 = packh2(s[2 * kt2][0],     s[2 * kt2][1]);
            uint32_t pa1 = packh2(s[2 * kt2][2],     s[2 * kt2][3]);
            uint32_t pa2 = packh2(s[2 * kt2 + 1][0], s[2 * kt2 + 1][1]);
            uint32_t pa3 = packh2(s[2 * kt2 + 1][2], s[2 * kt2 + 1][3]);
            #pragma unroll
            for (int np = 0; np < 4; np++) {
                int rrow = np * 16 + (lane >> 4) * 8 + (lane & 7);
                int ccol = kt2 * 16 + ((lane >> 3) & 1) * 8;
                uint32_t b0, b1, b2, b3;
                ldsm4(b0, b1, b2, b3, vbase + (uint32_t)(rrow * ASTR + ccol) * 2);
                MMA16(o[2 * np],     pa0, pa1, pa2, pa3, b0, b1);
                MMA16(o[2 * np + 1], pa0, pa1, pa2, pa3, b2, b3);
            }
        }
        __syncthreads();
    }

    // ---- epilogue: normalize, write half (B, T, H*Dh) ----
    const float inv0 = 1.0f / l0, inv1 = 1.0f / l1;
    const int bb = bh >> 4;
    __half* ob0 = out + ((size_t)(bb * T_ + wrow + r)) * D_ + h * DH_;
    __half* ob1 = out + ((size_t)(bb * T_ + wrow + r + 8)) * D_ + h * DH_;
    #pragma unroll
    for (int no = 0; no < 8; no++) {
        int c = no * 8 + 2 * ql;
        *(uint32_t*)(ob0 + c) = packh2(o[no][0] * inv0, o[no][1] * inv0);
        *(uint32_t*)(ob1 + c) = packh2(o[no][2] * inv1, o[no][3] * inv1);
    }
}

// ---------------------------------------------------------------------------
extern "C" void kernel_launch(void* const* d_in, const int* in_sizes, int n_in,
                              void* d_out, int out_size)
{
    const float* x  = (const float*)d_in[0];
    const float* wq = (const float*)d_in[1];
    const float* wk = (const float*)d_in[2];
    const float* wv = (const float*)d_in[3];
    const float* wo = (const float*)d_in[4];
    const float* bo = (const float*)d_in[5];

    __half *qp, *kp, *vtp, *ap, *xp, *wqp, *wkp, *wvp, *wop;
    cudaGetSymbolAddress((void**)&qp,  g_q);
    cudaGetSymbolAddress((void**)&kp,  g_k);
    cudaGetSymbolAddress((void**)&vtp, g_vt);
    cudaGetSymbolAddress((void**)&ap,  g_att);
    cudaGetSymbolAddress((void**)&xp,  g_x);
    cudaGetSymbolAddress((void**)&wqp, g_wq);
    cudaGetSymbolAddress((void**)&wkp, g_wk);
    cudaGetSymbolAddress((void**)&wvp, g_wv);
    cudaGetSymbolAddress((void**)&wop, g_wo);

    const int nx4 = M_ * D_ / 4, nw4 = D_ * D_ / 4;
    f2h_kernel<<<(nx4 + 255) / 256, 256>>>(x,  xp,  nx4);
    f2h_kernel<<<(nw4 + 255) / 256, 256>>>(wq, wqp, nw4);
    f2h_kernel<<<(nw4 + 255) / 256, 256>>>(wk, wkp, nw4);
    f2h_kernel<<<(nw4 + 255) / 256, 256>>>(wv, wvp, nw4);
    f2h_kernel<<<(nw4 + 255) / 256, 256>>>(wo, wop, nw4);

    cudaFuncSetAttribute(gemm_h<0>,
                         cudaFuncAttributeMaxDynamicSharedMemorySize, GEMM_SMEM);
    cudaFuncSetAttribute(gemm_h<1>,
                         cudaFuncAttributeMaxDynamicSharedMemorySize, GEMM_SMEM);
    cudaFuncSetAttribute(gemm_h<2>,
                         cudaFuncAttributeMaxDynamicSharedMemorySize, GEMM_SMEM);

    dim3 gg(D_ / 128, M_ / 128);   // (8, 64)
    gemm_h<0><<<gg, 256, GEMM_SMEM>>>(xp, wqp, nullptr, qp,  1.0f);
    gemm_h<0><<<gg, 256, GEMM_SMEM>>>(xp, wkp, nullptr, kp,  QSC);
    gemm_h<2><<<gg, 256, GEMM_SMEM>>>(xp, wvp, nullptr, vtp, 1.0f);

    attn_h<<<dim3(T_ / 128, B_ * H_), 256>>>(qp, kp, vtp, ap);

    gemm_h<1><<<gg, 256, GEMM_SMEM>>>(ap, wop, bo, d_out, 1.0f);
}